// round 15
// baseline (speedup 1.0000x reference)
#include <cuda_runtime.h>
#include <cuda_fp16.h>
#include <math.h>
#include <stdint.h>

#define HH 256
#define WW 256
#define CCH 256
#define NROI 1024
#define ICN 12544          // 256 * 49
#define FC 1024
#define NOUT 49
#define KSPLIT 4
#define KCH (ICN / KSPLIT)   // 3136

// ---------------- scratch (device globals; no allocations allowed) ----------
__device__ __align__(16) __half g_feat_h[(size_t)2 * 256 * 256 * 256]; // (B,H,W,C) fp16
__device__ __align__(16) __half g_xh[(size_t)NROI * ICN];    // x fp16 (n,HW,C)
__device__ __align__(16) __half g_w1h[(size_t)ICN * FC];     // w1 fp16, K-permuted
__device__ float g_w2t[NOUT * FC];                           // w2 transposed
__device__ float g_part[KSPLIT][(size_t)NROI * FC];          // split-K partials

__device__ __forceinline__ uint32_t smem_u32(const void* p) {
    return (uint32_t)__cvta_generic_to_shared(p);
}
__device__ __forceinline__ void cp_async16(uint32_t dst, const void* src) {
    asm volatile("cp.async.cg.shared.global [%0], [%1], 16;\n" :: "r"(dst), "l"(src));
}
#define CP_COMMIT() asm volatile("cp.async.commit_group;\n")
#define CP_WAIT(n)  asm volatile("cp.async.wait_group %0;\n" :: "n"(n))

// ---------------- kernel 1: transpose (B,C,H,W) fp32 -> (B,H,W,C) fp16 -------
__global__ void __launch_bounds__(256) transpose_kernel(const float* __restrict__ f) {
    __shared__ float tile[32][33];
    int b = blockIdx.z;
    int hw0 = blockIdx.x * 32;
    int c0 = blockIdx.y * 32;
    int t = threadIdx.x;

    int ty = t >> 3, tx = t & 7;
    const float* src = f + ((size_t)b * CCH + c0 + ty) * (HH * WW) + hw0 + tx * 4;
    float4 v = *(const float4*)src;
    tile[tx * 4 + 0][ty] = v.x;
    tile[tx * 4 + 1][ty] = v.y;
    tile[tx * 4 + 2][ty] = v.z;
    tile[tx * 4 + 3][ty] = v.w;
    __syncthreads();

    int r = t >> 3, q = t & 7;
    __half2 h0 = __floats2half2_rn(tile[r][q * 4 + 0], tile[r][q * 4 + 1]);
    __half2 h1 = __floats2half2_rn(tile[r][q * 4 + 2], tile[r][q * 4 + 3]);
    uint2 o;
    o.x = *(uint32_t*)&h0;
    o.y = *(uint32_t*)&h1;
    __half* dst = g_feat_h + ((size_t)b << 24) + (size_t)(hw0 + r) * CCH + c0 + q * 4;
    *(uint2*)dst = o;
}

// ---------------- kernel 2: rotated roi-align + fused conversions ------------
// grid (1024, 3): y<2 -> roi halves; y==2 -> conv_w1/conv_w2 work.
struct alignas(32) Samp4 { int o11, o12, o21, o22; float w11, w12, w21, w22; };

__device__ __forceinline__ void roi_bin4(const uint2* __restrict__ ft4,
                                         const Samp4* __restrict__ samp,
                                         int bl, float4& acc) {
    acc.x = 0.0f; acc.y = 0.0f; acc.z = 0.0f; acc.w = 0.0f;
#pragma unroll
    for (int s = 0; s < 4; s++) {
        const Samp4* sp = &samp[bl * 4 + s];
        int4 id = *(const int4*)(&sp->o11);
        float4 w = *(const float4*)(&sp->w11);
        uint2 v11 = ft4[id.x];
        uint2 v12 = ft4[id.y];
        uint2 v21 = ft4[id.z];
        uint2 v22 = ft4[id.w];
        float2 a11 = __half22float2(*(__half2*)&v11.x), b11 = __half22float2(*(__half2*)&v11.y);
        float2 a12 = __half22float2(*(__half2*)&v12.x), b12 = __half22float2(*(__half2*)&v12.y);
        float2 a21 = __half22float2(*(__half2*)&v21.x), b21 = __half22float2(*(__half2*)&v21.y);
        float2 a22 = __half22float2(*(__half2*)&v22.x), b22 = __half22float2(*(__half2*)&v22.y);
        acc.x += w.x * a11.x + w.y * a12.x + w.z * a21.x + w.w * a22.x;
        acc.y += w.x * a11.y + w.y * a12.y + w.z * a21.y + w.w * a22.y;
        acc.z += w.x * b11.x + w.y * b12.x + w.z * b21.x + w.w * b22.x;
        acc.w += w.x * b11.y + w.y * b12.y + w.z * b21.y + w.w * b22.y;
    }
}

__global__ void __launch_bounds__(256, 4) roi_kernel(const float* __restrict__ rois,
                                                     const float* __restrict__ w1,
                                                     const float* __restrict__ w2) {
    __shared__ Samp4 samp[196];
    int tid = threadIdx.x;

    if (blockIdx.y == 2) {
        // ---- fused conv_w2: first 196 blocks ----
        if (blockIdx.x < 196) {
            int i = blockIdx.x * 256 + tid;
            if (i < FC * NOUT) {
                int k = i / NOUT, o = i - k * NOUT;
                g_w2t[o * FC + k] = w2[i];
            }
        }
        // ---- fused conv_w1: strided over all 1024 blocks ----
#pragma unroll 1
        for (int kk = 0; kk < 7; kk++) {
            size_t i = (size_t)blockIdx.x * 256 + tid + (size_t)kk * (1024 * 256);
            if (i < (size_t)ICN * FC / 8) {
                int row = (int)(i >> 7);
                int col8 = (int)(i & 127);
                int c = row / 49, hw = row - c * 49;
                int nrow = hw * 256 + c;
                const float4* s = (const float4*)(w1 + (size_t)row * FC + col8 * 8);
                float4 a = s[0], bq = s[1];
                __half2 p0 = __floats2half2_rn(a.x, a.y);
                __half2 p1 = __floats2half2_rn(a.z, a.w);
                __half2 p2 = __floats2half2_rn(bq.x, bq.y);
                __half2 p3 = __floats2half2_rn(bq.z, bq.w);
                uint4 outv;
                outv.x = *(uint32_t*)&p0; outv.y = *(uint32_t*)&p1;
                outv.z = *(uint32_t*)&p2; outv.w = *(uint32_t*)&p3;
                *(uint4*)(g_w1h + (size_t)nrow * FC + col8 * 8) = outv;
            }
        }
        return;
    }

    int n = blockIdx.x;
    int half = blockIdx.y;

    const float* r = rois + n * 6;
    int b = (int)r[0];
    float cx = r[1] * 0.125f;
    float cy = r[2] * 0.125f;
    float rw = fmaxf(r[3] * 0.125f, 1.0f);
    float rh = fmaxf(r[4] * 0.125f, 1.0f);
    float theta = r[5];
    float st, ct;
    sincosf(theta, &st, &ct);
    float bw = rw / 7.0f;
    float bh = rh / 7.0f;

    if (tid < 196) {
        int bin = tid >> 2;
        int s = tid & 3;
        int ph = bin / 7, pw = bin - ph * 7;
        int sy = s >> 1, sx = s & 1;
        float yy = -rh * 0.5f + ((float)ph + 0.25f + 0.5f * (float)sy) * bh;
        float xx = -rw * 0.5f + ((float)pw + 0.25f + 0.5f * (float)sx) * bw;
        float xs = xx * ct - yy * st + cx;
        float ys = xx * st + yy * ct + cy;
        bool valid = (ys > -1.0f) && (ys < (float)HH) && (xs > -1.0f) && (xs < (float)WW);
        float ysc = fminf(fmaxf(ys, 0.0f), (float)(HH - 1));
        float xsc = fminf(fmaxf(xs, 0.0f), (float)(WW - 1));
        int yl = (int)floorf(ysc);
        int xl = (int)floorf(xsc);
        int yh = min(yl + 1, HH - 1);
        int xh = min(xl + 1, WW - 1);
        float ly = ysc - (float)yl;
        float lx = xsc - (float)xl;
        float hy = 1.0f - ly, hx = 1.0f - lx;
        float vf = valid ? 0.25f : 0.0f;
        Samp4 sp;
        // element offsets into uint2 (4-half) array: row stride 256h = 64 u2
        sp.o11 = (yl << 14) + (xl << 6);
        sp.o12 = (yl << 14) + (xh << 6);
        sp.o21 = (yh << 14) + (xl << 6);
        sp.o22 = (yh << 14) + (xh << 6);
        sp.w11 = hy * hx * vf; sp.w12 = hy * lx * vf;
        sp.w21 = ly * hx * vf; sp.w22 = ly * lx * vf;
        samp[tid] = sp;
    }
    __syncthreads();

    int c4 = tid & 63;         // channel quad: channels 4c4..4c4+3
    int sub = tid >> 6;        // 4-way bin interleave
    const uint2* ft4 = (const uint2*)(g_feat_h + ((size_t)b << 24)) + c4;
    __half* xh = g_xh + (size_t)n * ICN + 4 * c4;

    int bstart = half * 25;
    int bend = bstart + (half ? 24 : 25);

    int bl = bstart + sub;
#pragma unroll 1
    for (; bl + 4 < bend; bl += 8) {
        float4 a0, a1;
        roi_bin4(ft4, samp, bl, a0);
        roi_bin4(ft4, samp, bl + 4, a1);
        uint2 s0, s1;
        __half2 h;
        h = __floats2half2_rn(a0.x, a0.y); s0.x = *(uint32_t*)&h;
        h = __floats2half2_rn(a0.z, a0.w); s0.y = *(uint32_t*)&h;
        h = __floats2half2_rn(a1.x, a1.y); s1.x = *(uint32_t*)&h;
        h = __floats2half2_rn(a1.z, a1.w); s1.y = *(uint32_t*)&h;
        *(uint2*)(xh + bl * 256) = s0;
        *(uint2*)(xh + (bl + 4) * 256) = s1;
    }
    if (bl < bend) {
        float4 a0;
        roi_bin4(ft4, samp, bl, a0);
        uint2 s0;
        __half2 h;
        h = __floats2half2_rn(a0.x, a0.y); s0.x = *(uint32_t*)&h;
        h = __floats2half2_rn(a0.z, a0.w); s0.y = *(uint32_t*)&h;
        *(uint2*)(xh + bl * 256) = s0;
    }
}

// ---------------- kernel 3: GEMM1 split-K partials, fp16 HMMA ----------------
// BM=128, BN=128, BK=64, KSPLIT=4. grid (8,8,4), 256 threads (8 warps 4x2),
// warp tile 32x64. 3-stage cp.async pipeline, 96KB dynamic smem.
#define BM 128
#define BN 128
#define BK 64
#define KT2 (KCH / BK)     // 49
#define STG_A 16384
#define STG_B 16384
#define SB_OFF (3 * STG_A)

__device__ __forceinline__ void ldmatrix_x4(uint32_t* r, uint32_t addr) {
    asm volatile("ldmatrix.sync.aligned.m8n8.x4.shared.b16 {%0,%1,%2,%3}, [%4];"
                 : "=r"(r[0]), "=r"(r[1]), "=r"(r[2]), "=r"(r[3]) : "r"(addr));
}
__device__ __forceinline__ void ldmatrix_x4_trans(uint32_t* r, uint32_t addr) {
    asm volatile("ldmatrix.sync.aligned.m8n8.x4.trans.shared.b16 {%0,%1,%2,%3}, [%4];"
                 : "=r"(r[0]), "=r"(r[1]), "=r"(r[2]), "=r"(r[3]) : "r"(addr));
}

extern __shared__ uint8_t dynsm[];

__global__ void __launch_bounds__(256, 2) gemm1_kernel() {
    uint8_t* sA = dynsm;                 // [3][128 rows][128 B]
    uint8_t* sB = dynsm + SB_OFF;        // [3][64 rows][256 B]

    int t = threadIdx.x;
    int lane = t & 31, warp = t >> 5;
    int wm = warp >> 1, wn = warp & 1;
    int n0 = blockIdx.x * BN;
    int m0 = blockIdx.y * BM;
    int ks = blockIdx.z;

    int am = t & 127, ah = t >> 7;
    const uint8_t* agp = (const uint8_t*)(g_xh + (size_t)(m0 + am) * ICN + ks * KCH) + ah * 64;
    uint32_t aSm[4];
#pragma unroll
    for (int j = 0; j < 4; j++) {
        int q = ah * 4 + j;
        aSm[j] = smem_u32(sA + am * 128 + ((q ^ (am & 7)) << 4));
    }
    int bkr = t >> 2, bq0 = (t & 3) * 4;
    const uint8_t* bgp = (const uint8_t*)(g_w1h + (size_t)(ks * KCH + bkr) * FC + n0) + bq0 * 16;
    uint32_t bSm[4];
#pragma unroll
    for (int j = 0; j < 4; j++) {
        int q = bq0 + j;
        bSm[j] = smem_u32(sB + bkr * 256 + ((q >> 3) << 7) + (((q & 7) ^ (bkr & 7)) << 4));
    }
    const size_t bStepG = (size_t)BK * FC * 2;

    int mRow0 = wm * 32 + (lane & 15);
    int msw = mRow0 & 7;
    int aQsel = lane >> 4;
    uint32_t aBase0 = smem_u32(sA + mRow0 * 128);
    uint32_t aBase1 = aBase0 + 16 * 128;
    int bK = lane & 15;
    uint32_t bBaseRow = smem_u32(sB + bK * 256 + wn * 128);
    int physB[4];
#pragma unroll
    for (int g = 0; g < 4; g++)
        physB[g] = ((g * 2 + (lane >> 4)) ^ (bK & 7)) << 4;

    float acc[2][8][4];
#pragma unroll
    for (int mi = 0; mi < 2; mi++)
#pragma unroll
        for (int ni = 0; ni < 8; ni++)
#pragma unroll
            for (int j = 0; j < 4; j++) acc[mi][ni][j] = 0.0f;

#pragma unroll
    for (int s = 0; s < 2; s++) {
        uint32_t ao = s * STG_A, bo = s * STG_B;
        const uint8_t* ag = agp + (size_t)s * 128;
#pragma unroll
        for (int j = 0; j < 4; j++) cp_async16(aSm[j] + ao, ag + j * 16);
        const uint8_t* bg = bgp + (size_t)s * bStepG;
#pragma unroll
        for (int j = 0; j < 4; j++) cp_async16(bSm[j] + bo, bg + j * 16);
        CP_COMMIT();
    }

    int stage = 0;
    for (int kt = 0; kt < KT2; kt++) {
        CP_WAIT(1);
        __syncthreads();

        if (kt + 2 < KT2) {
            int ws = (stage + 2 >= 3) ? stage - 1 : stage + 2;
            uint32_t ao = ws * STG_A, bo = ws * STG_B;
            const uint8_t* ag = agp + (size_t)(kt + 2) * 128;
#pragma unroll
            for (int j = 0; j < 4; j++) cp_async16(aSm[j] + ao, ag + j * 16);
            const uint8_t* bg = bgp + (size_t)(kt + 2) * bStepG;
#pragma unroll
            for (int j = 0; j < 4; j++) cp_async16(bSm[j] + bo, bg + j * 16);
            CP_COMMIT();
        }

        uint32_t ao = stage * STG_A, bo = stage * STG_B;
#pragma unroll
        for (int kk = 0; kk < BK; kk += 16) {
            uint32_t a[2][4], b[4][4];
            int qa = (kk >> 3) + aQsel;
            uint32_t aoff = ao + (uint32_t)((qa ^ msw) << 4);
            ldmatrix_x4(a[0], aBase0 + aoff);
            ldmatrix_x4(a[1], aBase1 + aoff);
            uint32_t boff = bo + (uint32_t)(kk * 256);
#pragma unroll
            for (int g = 0; g < 4; g++)
                ldmatrix_x4_trans(b[g], bBaseRow + boff + physB[g]);
#pragma unroll
            for (int mi = 0; mi < 2; mi++)
#pragma unroll
                for (int ni = 0; ni < 8; ni++) {
                    uint32_t bb0 = b[ni >> 1][(ni & 1) * 2];
                    uint32_t bb1 = b[ni >> 1][(ni & 1) * 2 + 1];
                    asm volatile(
                        "mma.sync.aligned.m16n8k16.row.col.f32.f16.f16.f32 "
                        "{%0,%1,%2,%3}, {%4,%5,%6,%7}, {%8,%9}, {%0,%1,%2,%3};"
                        : "+f"(acc[mi][ni][0]), "+f"(acc[mi][ni][1]),
                          "+f"(acc[mi][ni][2]), "+f"(acc[mi][ni][3])
                        : "r"(a[mi][0]), "r"(a[mi][1]), "r"(a[mi][2]), "r"(a[mi][3]),
                          "r"(bb0), "r"(bb1));
                }
        }
        stage = (stage + 1 >= 3) ? 0 : stage + 1;
    }

    int tig = lane & 3;
    int gid = lane >> 2;
    float* pbase = g_part[ks];
#pragma unroll
    for (int mi = 0; mi < 2; mi++) {
        int row = m0 + wm * 32 + mi * 16 + gid;
#pragma unroll
        for (int ni = 0; ni < 8; ni++) {
            int col = n0 + wn * 64 + ni * 8 + tig * 2;
            *(float2*)(pbase + (size_t)row * FC + col) =
                make_float2(acc[mi][ni][0], acc[mi][ni][1]);
            *(float2*)(pbase + (size_t)(row + 8) * FC + col) =
                make_float2(acc[mi][ni][2], acc[mi][ni][3]);
        }
    }
}

// ---------------- kernel 4: fused tail: reduce + gemm2 + sigmoid + modulate --
// 1 block per roi, 256 threads, min 6 blocks/SM for occupancy.
#define MPAD 261
__global__ void __launch_bounds__(256, 6) tail_kernel(const float* __restrict__ b1,
                                                      const float* __restrict__ b2,
                                                      float* __restrict__ out) {
    __shared__ float hid[FC];          // 4KB
    __shared__ float msk[64];
    __shared__ float sh[25 * MPAD];    // 26.1KB
    int n = blockIdx.x;
    int tid = threadIdx.x;

    // ---- phase 1: reduce split-K partials + bias + relu -> smem hid ----
    {
        size_t ri = (size_t)n * (FC / 4) + tid;    // float4 index into roi row
        float4 p0 = ((const float4*)g_part[0])[ri];
        float4 p1 = ((const float4*)g_part[1])[ri];
        float4 p2 = ((const float4*)g_part[2])[ri];
        float4 p3 = ((const float4*)g_part[3])[ri];
        float4 bb = ((const float4*)b1)[tid];
        float4 h;
        h.x = fmaxf(p0.x + p1.x + p2.x + p3.x + bb.x, 0.0f);
        h.y = fmaxf(p0.y + p1.y + p2.y + p3.y + bb.y, 0.0f);
        h.z = fmaxf(p0.z + p1.z + p2.z + p3.z + bb.z, 0.0f);
        h.w = fmaxf(p0.w + p1.w + p2.w + p3.w + bb.w, 0.0f);
        ((float4*)hid)[tid] = h;
    }
    __syncthreads();

    // ---- phase 2: mask = sigmoid(hid @ w2 + b2) ----
    // Warp handles up to 7 outputs concurrently: one hid read feeds 7 FMA chains.
    {
        int warp = tid >> 5, lane = tid & 31;
        const float4* h4 = (const float4*)hid;
        float acc[7] = {0, 0, 0, 0, 0, 0, 0};
        const float4* wr[7];
#pragma unroll
        for (int j = 0; j < 7; j++) {
            int o = warp + 8 * j;
            wr[j] = (const float4*)(g_w2t + (size_t)(o < NOUT ? o : NOUT - 1) * FC);
        }
#pragma unroll
        for (int i = 0; i < 8; i++) {
            float4 x = h4[i * 32 + lane];
#pragma unroll
            for (int j = 0; j < 7; j++) {
                float4 w = wr[j][i * 32 + lane];
                acc[j] += w.x * x.x + w.y * x.y + w.z * x.z + w.w * x.w;
            }
        }
#pragma unroll
        for (int off = 16; off > 0; off >>= 1)
#pragma unroll
            for (int j = 0; j < 7; j++)
                acc[j] += __shfl_xor_sync(0xffffffffu, acc[j], off);
        if (lane == 0) {
#pragma unroll
            for (int j = 0; j < 7; j++) {
                int o = warp + 8 * j;
                if (o < NOUT)
                    msk[o] = 1.0f / (1.0f + expf(-(acc[j] + b2[o])));
            }
        }
    }
    __syncthreads();

    // ---- phase 3: out(n,c,hw) = xh(n,hw,c) * msk(hw), smem transpose ----
    const __half2* xs2 = (const __half2*)(g_xh + (size_t)n * ICN);
    float* o = out + (size_t)n * ICN;

    // chunk 0: hw 0..24
    for (int i = tid; i < 25 * 128; i += 256) {
        int hw = i >> 7, c2 = i & 127;
        float2 f = __half22float2(xs2[i]);
        sh[hw * MPAD + 2 * c2] = f.x;
        sh[hw * MPAD + 2 * c2 + 1] = f.y;
    }
    __syncthreads();
    for (int i = tid; i < 256 * 25; i += 256) {
        int c = i / 25, hw = i - c * 25;
        o[c * 49 + hw] = sh[hw * MPAD + c] * msk[hw];
    }
    __syncthreads();

    // chunk 1: hw 25..48
    for (int i = tid; i < 24 * 128; i += 256) {
        int hw = i >> 7, c2 = i & 127;
        float2 f = __half22float2(xs2[25 * 128 + i]);
        sh[hw * MPAD + 2 * c2] = f.x;
        sh[hw * MPAD + 2 * c2 + 1] = f.y;
    }
    __syncthreads();
    for (int i = tid; i < 256 * 24; i += 256) {
        int c = i / 24, hw = i - c * 24;
        o[c * 49 + 25 + hw] = sh[hw * MPAD + c] * msk[25 + hw];
    }
}

// ---------------- launcher ---------------------------------------------------
extern "C" void kernel_launch(void* const* d_in, const int* in_sizes, int n_in,
                              void* d_out, int out_size) {
    const float* features = (const float*)d_in[0];
    const float* rois     = (const float*)d_in[1];
    const float* w1       = (const float*)d_in[2];
    const float* b1       = (const float*)d_in[3];
    const float* w2       = (const float*)d_in[4];
    const float* b2       = (const float*)d_in[5];
    float* out = (float*)d_out;

    cudaFuncSetAttribute(gemm1_kernel,
                         cudaFuncAttributeMaxDynamicSharedMemorySize, 98304);

    transpose_kernel<<<dim3((HH * WW) / 32, CCH / 32, 2), 256>>>(features);
    roi_kernel<<<dim3(NROI, 3), 256>>>(rois, w1, w2);
    gemm1_kernel<<<dim3(FC / BN, NROI / BM, KSPLIT), 256, 98304>>>();
    tail_kernel<<<NROI, 256>>>(b1, b2, out);
}

// round 16
// speedup vs baseline: 1.0357x; 1.0357x over previous
#include <cuda_runtime.h>
#include <cuda_fp16.h>
#include <math.h>
#include <stdint.h>

#define HH 256
#define WW 256
#define CCH 256
#define NROI 1024
#define ICN 12544          // 256 * 49
#define FC 1024
#define NOUT 49
#define KSPLIT 4
#define KCH (ICN / KSPLIT)   // 3136

// ---------------- scratch (device globals; no allocations allowed) ----------
__device__ __align__(16) __half g_feat_h[(size_t)2 * 256 * 256 * 256]; // (B,H,W,C) fp16
__device__ __align__(16) __half g_xh[(size_t)NROI * ICN];    // x fp16 (n,HW,C)
__device__ __align__(16) __half g_w1h[(size_t)ICN * FC];     // w1 fp16, K-permuted
__device__ float g_w2t[NOUT * FC];                           // w2 transposed
__device__ float g_part[KSPLIT][(size_t)NROI * FC];          // split-K partials
__device__ float g_mask[NROI * NOUT];

__device__ __forceinline__ uint32_t smem_u32(const void* p) {
    return (uint32_t)__cvta_generic_to_shared(p);
}
__device__ __forceinline__ void cp_async16(uint32_t dst, const void* src) {
    asm volatile("cp.async.cg.shared.global [%0], [%1], 16;\n" :: "r"(dst), "l"(src));
}
#define CP_COMMIT() asm volatile("cp.async.commit_group;\n")
#define CP_WAIT(n)  asm volatile("cp.async.wait_group %0;\n" :: "n"(n))

// ---------------- kernel 1: transpose (B,C,H,W) fp32 -> (B,H,W,C) fp16 -------
__global__ void __launch_bounds__(256) transpose_kernel(const float* __restrict__ f) {
    __shared__ float tile[32][33];
    int b = blockIdx.z;
    int hw0 = blockIdx.x * 32;
    int c0 = blockIdx.y * 32;
    int t = threadIdx.x;

    int ty = t >> 3, tx = t & 7;
    const float* src = f + ((size_t)b * CCH + c0 + ty) * (HH * WW) + hw0 + tx * 4;
    float4 v = *(const float4*)src;
    tile[tx * 4 + 0][ty] = v.x;
    tile[tx * 4 + 1][ty] = v.y;
    tile[tx * 4 + 2][ty] = v.z;
    tile[tx * 4 + 3][ty] = v.w;
    __syncthreads();

    int r = t >> 3, q = t & 7;
    __half2 h0 = __floats2half2_rn(tile[r][q * 4 + 0], tile[r][q * 4 + 1]);
    __half2 h1 = __floats2half2_rn(tile[r][q * 4 + 2], tile[r][q * 4 + 3]);
    uint2 o;
    o.x = *(uint32_t*)&h0;
    o.y = *(uint32_t*)&h1;
    __half* dst = g_feat_h + ((size_t)b << 24) + (size_t)(hw0 + r) * CCH + c0 + q * 4;
    *(uint2*)dst = o;
}

// ---------------- kernel 2: rotated roi-align + fused conversions ------------
// grid (1024, 3): y<2 -> roi halves; y==2 -> conv_w1/conv_w2 work.
struct alignas(32) Samp4 { int o11, o12, o21, o22; float w11, w12, w21, w22; };

__device__ __forceinline__ void roi_bin4(const uint2* __restrict__ ft4,
                                         const Samp4* __restrict__ samp,
                                         int bl, float4& acc) {
    acc.x = 0.0f; acc.y = 0.0f; acc.z = 0.0f; acc.w = 0.0f;
#pragma unroll
    for (int s = 0; s < 4; s++) {
        const Samp4* sp = &samp[bl * 4 + s];
        int4 id = *(const int4*)(&sp->o11);
        float4 w = *(const float4*)(&sp->w11);
        uint2 v11 = ft4[id.x];
        uint2 v12 = ft4[id.y];
        uint2 v21 = ft4[id.z];
        uint2 v22 = ft4[id.w];
        float2 a11 = __half22float2(*(__half2*)&v11.x), b11 = __half22float2(*(__half2*)&v11.y);
        float2 a12 = __half22float2(*(__half2*)&v12.x), b12 = __half22float2(*(__half2*)&v12.y);
        float2 a21 = __half22float2(*(__half2*)&v21.x), b21 = __half22float2(*(__half2*)&v21.y);
        float2 a22 = __half22float2(*(__half2*)&v22.x), b22 = __half22float2(*(__half2*)&v22.y);
        acc.x += w.x * a11.x + w.y * a12.x + w.z * a21.x + w.w * a22.x;
        acc.y += w.x * a11.y + w.y * a12.y + w.z * a21.y + w.w * a22.y;
        acc.z += w.x * b11.x + w.y * b12.x + w.z * b21.x + w.w * b22.x;
        acc.w += w.x * b11.y + w.y * b12.y + w.z * b21.y + w.w * b22.y;
    }
}

__global__ void __launch_bounds__(256, 4) roi_kernel(const float* __restrict__ rois,
                                                     const float* __restrict__ w1,
                                                     const float* __restrict__ w2) {
    __shared__ Samp4 samp[196];
    int tid = threadIdx.x;

    if (blockIdx.y == 2) {
        // ---- fused conv_w2: first 196 blocks ----
        if (blockIdx.x < 196) {
            int i = blockIdx.x * 256 + tid;
            if (i < FC * NOUT) {
                int k = i / NOUT, o = i - k * NOUT;
                g_w2t[o * FC + k] = w2[i];
            }
        }
        // ---- fused conv_w1: strided over all 1024 blocks ----
#pragma unroll 1
        for (int kk = 0; kk < 7; kk++) {
            size_t i = (size_t)blockIdx.x * 256 + tid + (size_t)kk * (1024 * 256);
            if (i < (size_t)ICN * FC / 8) {
                int row = (int)(i >> 7);
                int col8 = (int)(i & 127);
                int c = row / 49, hw = row - c * 49;
                int nrow = hw * 256 + c;
                const float4* s = (const float4*)(w1 + (size_t)row * FC + col8 * 8);
                float4 a = s[0], bq = s[1];
                __half2 p0 = __floats2half2_rn(a.x, a.y);
                __half2 p1 = __floats2half2_rn(a.z, a.w);
                __half2 p2 = __floats2half2_rn(bq.x, bq.y);
                __half2 p3 = __floats2half2_rn(bq.z, bq.w);
                uint4 outv;
                outv.x = *(uint32_t*)&p0; outv.y = *(uint32_t*)&p1;
                outv.z = *(uint32_t*)&p2; outv.w = *(uint32_t*)&p3;
                *(uint4*)(g_w1h + (size_t)nrow * FC + col8 * 8) = outv;
            }
        }
        return;
    }

    int n = blockIdx.x;
    int half = blockIdx.y;

    const float* r = rois + n * 6;
    int b = (int)r[0];
    float cx = r[1] * 0.125f;
    float cy = r[2] * 0.125f;
    float rw = fmaxf(r[3] * 0.125f, 1.0f);
    float rh = fmaxf(r[4] * 0.125f, 1.0f);
    float theta = r[5];
    float st, ct;
    sincosf(theta, &st, &ct);
    float bw = rw / 7.0f;
    float bh = rh / 7.0f;

    if (tid < 196) {
        int bin = tid >> 2;
        int s = tid & 3;
        int ph = bin / 7, pw = bin - ph * 7;
        int sy = s >> 1, sx = s & 1;
        float yy = -rh * 0.5f + ((float)ph + 0.25f + 0.5f * (float)sy) * bh;
        float xx = -rw * 0.5f + ((float)pw + 0.25f + 0.5f * (float)sx) * bw;
        float xs = xx * ct - yy * st + cx;
        float ys = xx * st + yy * ct + cy;
        bool valid = (ys > -1.0f) && (ys < (float)HH) && (xs > -1.0f) && (xs < (float)WW);
        float ysc = fminf(fmaxf(ys, 0.0f), (float)(HH - 1));
        float xsc = fminf(fmaxf(xs, 0.0f), (float)(WW - 1));
        int yl = (int)floorf(ysc);
        int xl = (int)floorf(xsc);
        int yh = min(yl + 1, HH - 1);
        int xh = min(xl + 1, WW - 1);
        float ly = ysc - (float)yl;
        float lx = xsc - (float)xl;
        float hy = 1.0f - ly, hx = 1.0f - lx;
        float vf = valid ? 0.25f : 0.0f;
        Samp4 sp;
        // element offsets into uint2 (4-half) array: row stride 256h = 64 u2
        sp.o11 = (yl << 14) + (xl << 6);
        sp.o12 = (yl << 14) + (xh << 6);
        sp.o21 = (yh << 14) + (xl << 6);
        sp.o22 = (yh << 14) + (xh << 6);
        sp.w11 = hy * hx * vf; sp.w12 = hy * lx * vf;
        sp.w21 = ly * hx * vf; sp.w22 = ly * lx * vf;
        samp[tid] = sp;
    }
    __syncthreads();

    int c4 = tid & 63;         // channel quad: channels 4c4..4c4+3
    int sub = tid >> 6;        // 4-way bin interleave
    const uint2* ft4 = (const uint2*)(g_feat_h + ((size_t)b << 24)) + c4;
    __half* xh = g_xh + (size_t)n * ICN + 4 * c4;

    int bstart = half * 25;
    int bend = bstart + (half ? 24 : 25);

    int bl = bstart + sub;
#pragma unroll 1
    for (; bl + 4 < bend; bl += 8) {
        float4 a0, a1;
        roi_bin4(ft4, samp, bl, a0);
        roi_bin4(ft4, samp, bl + 4, a1);
        uint2 s0, s1;
        __half2 h;
        h = __floats2half2_rn(a0.x, a0.y); s0.x = *(uint32_t*)&h;
        h = __floats2half2_rn(a0.z, a0.w); s0.y = *(uint32_t*)&h;
        h = __floats2half2_rn(a1.x, a1.y); s1.x = *(uint32_t*)&h;
        h = __floats2half2_rn(a1.z, a1.w); s1.y = *(uint32_t*)&h;
        *(uint2*)(xh + bl * 256) = s0;
        *(uint2*)(xh + (bl + 4) * 256) = s1;
    }
    if (bl < bend) {
        float4 a0;
        roi_bin4(ft4, samp, bl, a0);
        uint2 s0;
        __half2 h;
        h = __floats2half2_rn(a0.x, a0.y); s0.x = *(uint32_t*)&h;
        h = __floats2half2_rn(a0.z, a0.w); s0.y = *(uint32_t*)&h;
        *(uint2*)(xh + bl * 256) = s0;
    }
}

// ---------------- kernel 3: GEMM1 split-K partials, fp16 HMMA ----------------
// BM=128, BN=128, BK=64, KSPLIT=4. grid (8,8,4), 256 threads (8 warps 4x2),
// warp tile 32x64. 3-stage cp.async pipeline, 96KB dynamic smem.
#define BM 128
#define BN 128
#define BK 64
#define KT2 (KCH / BK)     // 49
#define STG_A 16384
#define STG_B 16384
#define SB_OFF (3 * STG_A)

__device__ __forceinline__ void ldmatrix_x4(uint32_t* r, uint32_t addr) {
    asm volatile("ldmatrix.sync.aligned.m8n8.x4.shared.b16 {%0,%1,%2,%3}, [%4];"
                 : "=r"(r[0]), "=r"(r[1]), "=r"(r[2]), "=r"(r[3]) : "r"(addr));
}
__device__ __forceinline__ void ldmatrix_x4_trans(uint32_t* r, uint32_t addr) {
    asm volatile("ldmatrix.sync.aligned.m8n8.x4.trans.shared.b16 {%0,%1,%2,%3}, [%4];"
                 : "=r"(r[0]), "=r"(r[1]), "=r"(r[2]), "=r"(r[3]) : "r"(addr));
}

extern __shared__ uint8_t dynsm[];

__global__ void __launch_bounds__(256, 2) gemm1_kernel() {
    uint8_t* sA = dynsm;                 // [3][128 rows][128 B]
    uint8_t* sB = dynsm + SB_OFF;        // [3][64 rows][256 B]

    int t = threadIdx.x;
    int lane = t & 31, warp = t >> 5;
    int wm = warp >> 1, wn = warp & 1;
    int n0 = blockIdx.x * BN;
    int m0 = blockIdx.y * BM;
    int ks = blockIdx.z;

    int am = t & 127, ah = t >> 7;
    const uint8_t* agp = (const uint8_t*)(g_xh + (size_t)(m0 + am) * ICN + ks * KCH) + ah * 64;
    uint32_t aSm[4];
#pragma unroll
    for (int j = 0; j < 4; j++) {
        int q = ah * 4 + j;
        aSm[j] = smem_u32(sA + am * 128 + ((q ^ (am & 7)) << 4));
    }
    int bkr = t >> 2, bq0 = (t & 3) * 4;
    const uint8_t* bgp = (const uint8_t*)(g_w1h + (size_t)(ks * KCH + bkr) * FC + n0) + bq0 * 16;
    uint32_t bSm[4];
#pragma unroll
    for (int j = 0; j < 4; j++) {
        int q = bq0 + j;
        bSm[j] = smem_u32(sB + bkr * 256 + ((q >> 3) << 7) + (((q & 7) ^ (bkr & 7)) << 4));
    }
    const size_t bStepG = (size_t)BK * FC * 2;

    int mRow0 = wm * 32 + (lane & 15);
    int msw = mRow0 & 7;
    int aQsel = lane >> 4;
    uint32_t aBase0 = smem_u32(sA + mRow0 * 128);
    uint32_t aBase1 = aBase0 + 16 * 128;
    int bK = lane & 15;
    uint32_t bBaseRow = smem_u32(sB + bK * 256 + wn * 128);
    int physB[4];
#pragma unroll
    for (int g = 0; g < 4; g++)
        physB[g] = ((g * 2 + (lane >> 4)) ^ (bK & 7)) << 4;

    float acc[2][8][4];
#pragma unroll
    for (int mi = 0; mi < 2; mi++)
#pragma unroll
        for (int ni = 0; ni < 8; ni++)
#pragma unroll
            for (int j = 0; j < 4; j++) acc[mi][ni][j] = 0.0f;

#pragma unroll
    for (int s = 0; s < 2; s++) {
        uint32_t ao = s * STG_A, bo = s * STG_B;
        const uint8_t* ag = agp + (size_t)s * 128;
#pragma unroll
        for (int j = 0; j < 4; j++) cp_async16(aSm[j] + ao, ag + j * 16);
        const uint8_t* bg = bgp + (size_t)s * bStepG;
#pragma unroll
        for (int j = 0; j < 4; j++) cp_async16(bSm[j] + bo, bg + j * 16);
        CP_COMMIT();
    }

    int stage = 0;
    for (int kt = 0; kt < KT2; kt++) {
        CP_WAIT(1);
        __syncthreads();

        if (kt + 2 < KT2) {
            int ws = (stage + 2 >= 3) ? stage - 1 : stage + 2;
            uint32_t ao = ws * STG_A, bo = ws * STG_B;
            const uint8_t* ag = agp + (size_t)(kt + 2) * 128;
#pragma unroll
            for (int j = 0; j < 4; j++) cp_async16(aSm[j] + ao, ag + j * 16);
            const uint8_t* bg = bgp + (size_t)(kt + 2) * bStepG;
#pragma unroll
            for (int j = 0; j < 4; j++) cp_async16(bSm[j] + bo, bg + j * 16);
            CP_COMMIT();
        }

        uint32_t ao = stage * STG_A, bo = stage * STG_B;
#pragma unroll
        for (int kk = 0; kk < BK; kk += 16) {
            uint32_t a[2][4], b[4][4];
            int qa = (kk >> 3) + aQsel;
            uint32_t aoff = ao + (uint32_t)((qa ^ msw) << 4);
            ldmatrix_x4(a[0], aBase0 + aoff);
            ldmatrix_x4(a[1], aBase1 + aoff);
            uint32_t boff = bo + (uint32_t)(kk * 256);
#pragma unroll
            for (int g = 0; g < 4; g++)
                ldmatrix_x4_trans(b[g], bBaseRow + boff + physB[g]);
#pragma unroll
            for (int mi = 0; mi < 2; mi++)
#pragma unroll
                for (int ni = 0; ni < 8; ni++) {
                    uint32_t bb0 = b[ni >> 1][(ni & 1) * 2];
                    uint32_t bb1 = b[ni >> 1][(ni & 1) * 2 + 1];
                    asm volatile(
                        "mma.sync.aligned.m16n8k16.row.col.f32.f16.f16.f32 "
                        "{%0,%1,%2,%3}, {%4,%5,%6,%7}, {%8,%9}, {%0,%1,%2,%3};"
                        : "+f"(acc[mi][ni][0]), "+f"(acc[mi][ni][1]),
                          "+f"(acc[mi][ni][2]), "+f"(acc[mi][ni][3])
                        : "r"(a[mi][0]), "r"(a[mi][1]), "r"(a[mi][2]), "r"(a[mi][3]),
                          "r"(bb0), "r"(bb1));
                }
        }
        stage = (stage + 1 >= 3) ? 0 : stage + 1;
    }

    int tig = lane & 3;
    int gid = lane >> 2;
    float* pbase = g_part[ks];
#pragma unroll
    for (int mi = 0; mi < 2; mi++) {
        int row = m0 + wm * 32 + mi * 16 + gid;
#pragma unroll
        for (int ni = 0; ni < 8; ni++) {
            int col = n0 + wn * 64 + ni * 8 + tig * 2;
            *(float2*)(pbase + (size_t)row * FC + col) =
                make_float2(acc[mi][ni][0], acc[mi][ni][1]);
            *(float2*)(pbase + (size_t)(row + 8) * FC + col) =
                make_float2(acc[mi][ni][2], acc[mi][ni][3]);
        }
    }
}

// ---------------- kernel 4: mask = sigmoid(relu(reduce(part)+b1) @ w2 + b2) --
// 4 rois per block, 256 blocks. w2t row read once per block serves 4 rois.
__global__ void __launch_bounds__(256) mask_kernel(const float* __restrict__ b1,
                                                   const float* __restrict__ b2) {
    __shared__ float hid[4][FC];       // 16KB
    int n0 = blockIdx.x * 4;
    int tid = threadIdx.x;

    // ---- phase 1: reduce split-K partials + bias + relu for 4 rois ----
    float4 bb = ((const float4*)b1)[tid];
#pragma unroll
    for (int r = 0; r < 4; r++) {
        size_t ri = (size_t)(n0 + r) * (FC / 4) + tid;
        float4 p0 = ((const float4*)g_part[0])[ri];
        float4 p1 = ((const float4*)g_part[1])[ri];
        float4 p2 = ((const float4*)g_part[2])[ri];
        float4 p3 = ((const float4*)g_part[3])[ri];
        float4 h;
        h.x = fmaxf(p0.x + p1.x + p2.x + p3.x + bb.x, 0.0f);
        h.y = fmaxf(p0.y + p1.y + p2.y + p3.y + bb.y, 0.0f);
        h.z = fmaxf(p0.z + p1.z + p2.z + p3.z + bb.z, 0.0f);
        h.w = fmaxf(p0.w + p1.w + p2.w + p3.w + bb.w, 0.0f);
        ((float4*)hid[r])[tid] = h;
    }
    __syncthreads();

    // ---- phase 2: warp per output, 4-roi ILP ----
    int warp = tid >> 5, lane = tid & 31;
    const float4* h0 = (const float4*)hid[0];
    const float4* h1 = (const float4*)hid[1];
    const float4* h2 = (const float4*)hid[2];
    const float4* h3 = (const float4*)hid[3];
#pragma unroll 1
    for (int o = warp; o < NOUT; o += 8) {
        const float4* wr = (const float4*)(g_w2t + (size_t)o * FC);
        float a0 = 0.0f, a1 = 0.0f, a2 = 0.0f, a3 = 0.0f;
#pragma unroll
        for (int i = 0; i < 8; i++) {
            float4 w = wr[i * 32 + lane];
            float4 x0 = h0[i * 32 + lane];
            float4 x1 = h1[i * 32 + lane];
            float4 x2 = h2[i * 32 + lane];
            float4 x3 = h3[i * 32 + lane];
            a0 += w.x * x0.x + w.y * x0.y + w.z * x0.z + w.w * x0.w;
            a1 += w.x * x1.x + w.y * x1.y + w.z * x1.z + w.w * x1.w;
            a2 += w.x * x2.x + w.y * x2.y + w.z * x2.z + w.w * x2.w;
            a3 += w.x * x3.x + w.y * x3.y + w.z * x3.z + w.w * x3.w;
        }
#pragma unroll
        for (int off = 16; off > 0; off >>= 1) {
            a0 += __shfl_xor_sync(0xffffffffu, a0, off);
            a1 += __shfl_xor_sync(0xffffffffu, a1, off);
            a2 += __shfl_xor_sync(0xffffffffu, a2, off);
            a3 += __shfl_xor_sync(0xffffffffu, a3, off);
        }
        if (lane == 0) {
            float bbv = b2[o];
            g_mask[(n0 + 0) * NOUT + o] = 1.0f / (1.0f + expf(-(a0 + bbv)));
            g_mask[(n0 + 1) * NOUT + o] = 1.0f / (1.0f + expf(-(a1 + bbv)));
            g_mask[(n0 + 2) * NOUT + o] = 1.0f / (1.0f + expf(-(a2 + bbv)));
            g_mask[(n0 + 3) * NOUT + o] = 1.0f / (1.0f + expf(-(a3 + bbv)));
        }
    }
}

// ---------------- kernel 5: modulate with fully vectorized output ------------
// grid (1024, 2): block builds contiguous out span for 128 channels in smem,
// then streams it with perfect float4 stores.
#define HC 128
__global__ void __launch_bounds__(256) modulate_kernel(float* __restrict__ out) {
    __shared__ float so[HC * 49];      // 25.1KB, laid out (c_local*49 + hw)
    __shared__ float msk[52];
    int n = blockIdx.x;
    int c0 = blockIdx.y * HC;
    int tid = threadIdx.x;

    if (tid < NOUT) msk[tid] = g_mask[n * NOUT + tid];
    __syncthreads();

    // fill: coalesced half2 reads of xh(hw, c), multiply by msk at fill
    const __half2* xs2 = (const __half2*)(g_xh + (size_t)n * ICN);
    int c0h = c0 >> 1;   // half2 offset of channel block
#pragma unroll 1
    for (int i = tid; i < 49 * 64; i += 256) {
        int hw = i >> 6;
        int c2 = i & 63;
        float2 f = __half22float2(xs2[hw * 128 + c0h + c2]);
        float m = msk[hw];
        so[(2 * c2) * 49 + hw] = f.x * m;
        so[(2 * c2 + 1) * 49 + hw] = f.y * m;
    }
    __syncthreads();

    // stream out: 1568 float4, perfectly coalesced
    const float4* s4 = (const float4*)so;
    float4* o4 = (float4*)(out + (size_t)n * ICN + (size_t)c0 * 49);
#pragma unroll 1
    for (int i = tid; i < HC * 49 / 4; i += 256)
        o4[i] = s4[i];
}

// ---------------- launcher ---------------------------------------------------
extern "C" void kernel_launch(void* const* d_in, const int* in_sizes, int n_in,
                              void* d_out, int out_size) {
    const float* features = (const float*)d_in[0];
    const float* rois     = (const float*)d_in[1];
    const float* w1       = (const float*)d_in[2];
    const float* b1       = (const float*)d_in[3];
    const float* w2       = (const float*)d_in[4];
    const float* b2       = (const float*)d_in[5];
    float* out = (float*)d_out;

    cudaFuncSetAttribute(gemm1_kernel,
                         cudaFuncAttributeMaxDynamicSharedMemorySize, 98304);

    transpose_kernel<<<dim3((HH * WW) / 32, CCH / 32, 2), 256>>>(features);
    roi_kernel<<<dim3(NROI, 3), 256>>>(rois, w1, w2);
    gemm1_kernel<<<dim3(FC / BN, NROI / BM, KSPLIT), 256, 98304>>>();
    mask_kernel<<<NROI / 4, 256>>>(b1, b2);
    modulate_kernel<<<dim3(NROI, 2), 256>>>(out);
}